// round 9
// baseline (speedup 1.0000x reference)
#include <cuda_runtime.h>
#include <cuda_bf16.h>
#include <cstdint>

#define GRAPHS 512
#define CDIM 256

// ---- device scratch (no allocations allowed) ----
// Per-kt fused weight stages: [kt][s][ntp][lane] uint4; s=0 gate, s=1 lin.
// One kt stage = 2*16*32 uint4 = 16 KB. Total 16 stages = 256 KB.
__device__ uint4 g_Bfrag[16 * 2 * 16 * 32];
__device__ float g_sums[GRAPHS * CDIM];       // 512 KB: pooled sums

static __device__ __forceinline__ uint32_t packbf(float a, float b) {
    __nv_bfloat162 h = __float22bfloat162_rn(make_float2(a, b));
    return *reinterpret_cast<uint32_t*>(&h);
}

// ---------------------------------------------------------------------------
__global__ void zero_sums_kernel() {
    int i = blockIdx.x * blockDim.x + threadIdx.x;
    if (i < GRAPHS * CDIM) g_sums[i] = 0.f;
}

// Pack W_gate (s=0) and W_lin (s=1), paired n-tiles, grouped per kt:
// e = ((kt*2 + s)*16 + ntp)*32 + lane
// n0 = ntp*16 + lane/4, n1 = n0+8, k0 = kt*16 + (lane%4)*2
__global__ void prep_weights_kernel(const float* __restrict__ Wg,
                                    const float* __restrict__ Wl) {
    int i = blockIdx.x * blockDim.x + threadIdx.x;
    if (i >= 16 * 2 * 16 * 32) return;
    int lane = i & 31;
    int ntp  = (i >> 5) & 15;
    int s    = (i >> 9) & 1;
    int kt   = i >> 10;
    const float* W = s ? Wl : Wg;
    int n0 = ntp * 16 + (lane >> 2);
    int n1 = n0 + 8;
    int k0 = kt * 16 + (lane & 3) * 2;
    uint4 v;
    v.x = packbf(W[(k0 + 0) * CDIM + n0], W[(k0 + 1) * CDIM + n0]);
    v.y = packbf(W[(k0 + 8) * CDIM + n0], W[(k0 + 9) * CDIM + n0]);
    v.z = packbf(W[(k0 + 0) * CDIM + n1], W[(k0 + 1) * CDIM + n1]);
    v.w = packbf(W[(k0 + 8) * CDIM + n1], W[(k0 + 9) * CDIM + n1]);
    g_Bfrag[i] = v;
}

// ---------------------------------------------------------------------------
static __device__ __forceinline__ void mma_bf16(float acc[4],
                                                uint32_t a0, uint32_t a1,
                                                uint32_t a2, uint32_t a3,
                                                uint32_t b0, uint32_t b1) {
    asm volatile(
        "mma.sync.aligned.m16n8k16.row.col.f32.bf16.bf16.f32 "
        "{%0,%1,%2,%3}, {%4,%5,%6,%7}, {%8,%9}, {%0,%1,%2,%3};\n"
        : "+f"(acc[0]), "+f"(acc[1]), "+f"(acc[2]), "+f"(acc[3])
        : "r"(a0), "r"(a1), "r"(a2), "r"(a3), "r"(b0), "r"(b1));
}

static __device__ __forceinline__ void ldsm4(uint32_t& a0, uint32_t& a1,
                                             uint32_t& a2, uint32_t& a3,
                                             uint32_t addr) {
    asm volatile("ldmatrix.sync.aligned.m8n8.x4.shared.b16 {%0,%1,%2,%3}, [%4];"
                 : "=r"(a0), "=r"(a1), "=r"(a2), "=r"(a3) : "r"(addr));
}

static __device__ __forceinline__ void cp_async16(uint32_t smem_dst, const void* gsrc) {
    asm volatile("cp.async.cg.shared.global [%0], [%1], 16;\n"
                 :: "r"(smem_dst), "l"(gsrc));
}
static __device__ __forceinline__ void cp_commit() {
    asm volatile("cp.async.commit_group;\n");
}
static __device__ __forceinline__ void cp_wait2() {
    asm volatile("cp.async.wait_group 2;\n");
}

// Fused single-pass: gate GEMM and state GEMM share one A-fragment load per kt.
// Block: 64 nodes, 512 threads (16 warps = 2 row groups x 8 col groups).
// Warp tile: 32 rows (2 m16 strips) x 32 cols (4 n-tiles).
// 16 kt iterations total (vs 32 in the two-pass design); no gate staging pass.
#define XS_STRIDE 132                  // 128 uint32 + 4 pad
#define STAGE_U4  1024                 // one kt stage: 2 slabs * 512 uint4 (16 KB)
// dynamic smem layout (bytes):
#define XS_OFF     0                   // 64*132*4 = 33792
#define BSM_OFF    33792               // 3*16384  = 49152
#define BIAS_OFF   82944               // 512*4    = 2048
#define RMAX_OFF   84992               // 512*4    = 2048
#define RSUM_OFF   87040               // 512*4    = 2048
#define BID_OFF    89088               // 64*4
#define SMEM_TOTAL 89344

__global__ __launch_bounds__(512, 1) void main_kernel(
    const float* __restrict__ x, const int* __restrict__ batch,
    const float* __restrict__ b_lin, const float* __restrict__ b_gate, int N) {
    extern __shared__ char smraw[];
    uint32_t* xs     = reinterpret_cast<uint32_t*>(smraw + XS_OFF);
    uint4*    bsm    = reinterpret_cast<uint4*>(smraw + BSM_OFF);
    float*    bias   = reinterpret_cast<float*>(smraw + BIAS_OFF);
    float*    redmax = reinterpret_cast<float*>(smraw + RMAX_OFF);
    float*    redsum = reinterpret_cast<float*>(smraw + RSUM_OFF);
    int*      bid    = reinterpret_cast<int*>(smraw + BID_OFF);

    const int tid   = threadIdx.x;
    const int node0 = blockIdx.x * 64;

    const uint32_t bsm_s = (uint32_t)__cvta_generic_to_shared(bsm);
    const uint32_t xs_s  = (uint32_t)__cvta_generic_to_shared(xs);

    // prefetch kt stages 0,1 (16 KB each; 2 cp.async16 per thread per stage)
    {
        const char* s0 = (const char*)(g_Bfrag + (size_t)0 * STAGE_U4);
        cp_async16(bsm_s + 0 * 16384 + tid * 16, s0 + tid * 16);
        cp_async16(bsm_s + 0 * 16384 + (tid + 512) * 16, s0 + (tid + 512) * 16);
        cp_commit();
        const char* s1 = (const char*)(g_Bfrag + (size_t)1 * STAGE_U4);
        cp_async16(bsm_s + 1 * 16384 + tid * 16, s1 + tid * 16);
        cp_async16(bsm_s + 1 * 16384 + (tid + 512) * 16, s1 + (tid + 512) * 16);
        cp_commit();
    }

    // load x tile as packed bf16x2 (coalesced float2 reads)
    for (int i = tid; i < 64 * 128; i += 512) {
        int r = i >> 7, cp = i & 127;
        float2 v = make_float2(0.f, 0.f);
        if (node0 + r < N)
            v = reinterpret_cast<const float2*>(x)[(size_t)(node0 + r) * 128 + cp];
        xs[r * XS_STRIDE + cp] = packbf(v.x, v.y);
    }
    bias[tid] = (tid < 256) ? b_gate[tid] : b_lin[tid - 256];
    if (tid < 64) {
        int nd = node0 + tid;
        bid[tid] = (nd < N) ? batch[nd] : -1;
    }
    __syncthreads();

    const int lane = tid & 31, w = tid >> 5;
    const int wr = w >> 3;                // row group 0..1 (32 rows each)
    const int wq = w & 7;                 // col group 0..7 (32 cols each)
    const int r0 = wr * 32, gid = lane >> 2, tg = lane & 3;
    const int ra0 = r0 + gid,      rb0 = ra0 + 8;
    const int ra1 = r0 + 16 + gid, rb1 = ra1 + 8;
    const int rows[4] = {ra0, rb0, ra1, rb1};

    const int lr = ((lane >> 3) & 1) * 8 + (lane & 7);
    const uint32_t a_addr0 = xs_s + 4u * (uint32_t)((r0 + lr) * XS_STRIDE + (lane >> 4) * 4);
    const uint32_t a_addr1 = xs_s + 4u * (uint32_t)((r0 + 16 + lr) * XS_STRIDE + (lane >> 4) * 4);

    // accumulators: [strip][nt][frag]
    float gate[2][4][4], lin[2][4][4];
    #pragma unroll
    for (int s = 0; s < 2; s++)
        #pragma unroll
        for (int t = 0; t < 4; t++)
            #pragma unroll
            for (int k = 0; k < 4; k++) { gate[s][t][k] = 0.f; lin[s][t][k] = 0.f; }

    // ================= fused GEMM loop (16 kt) ==============================
    for (int kt = 0; kt < 16; kt++) {
        cp_wait2();
        __syncthreads();
        int nxt = kt + 2;
        if (nxt < 16) {
            const char* src = (const char*)(g_Bfrag + (size_t)nxt * STAGE_U4);
            uint32_t dst = bsm_s + (nxt % 3) * 16384;
            cp_async16(dst + tid * 16, src + tid * 16);
            cp_async16(dst + (tid + 512) * 16, src + (tid + 512) * 16);
        }
        cp_commit();
        uint32_t a0, a1, a2, a3, c0, c1, c2, c3;
        ldsm4(a0, a1, a2, a3, a_addr0 + (uint32_t)kt * 32);
        ldsm4(c0, c1, c2, c3, a_addr1 + (uint32_t)kt * 32);
        const uint4* st = bsm + (kt % 3) * STAGE_U4;
        uint4 bg0 = st[(0 * 16 + wq * 2 + 0) * 32 + lane];
        uint4 bg1 = st[(0 * 16 + wq * 2 + 1) * 32 + lane];
        uint4 bl0 = st[(1 * 16 + wq * 2 + 0) * 32 + lane];
        uint4 bl1 = st[(1 * 16 + wq * 2 + 1) * 32 + lane];
        mma_bf16(gate[0][0], a0, a1, a2, a3, bg0.x, bg0.y);
        mma_bf16(gate[0][1], a0, a1, a2, a3, bg0.z, bg0.w);
        mma_bf16(gate[0][2], a0, a1, a2, a3, bg1.x, bg1.y);
        mma_bf16(gate[0][3], a0, a1, a2, a3, bg1.z, bg1.w);
        mma_bf16(gate[1][0], c0, c1, c2, c3, bg0.x, bg0.y);
        mma_bf16(gate[1][1], c0, c1, c2, c3, bg0.z, bg0.w);
        mma_bf16(gate[1][2], c0, c1, c2, c3, bg1.x, bg1.y);
        mma_bf16(gate[1][3], c0, c1, c2, c3, bg1.z, bg1.w);
        mma_bf16(lin[0][0],  a0, a1, a2, a3, bl0.x, bl0.y);
        mma_bf16(lin[0][1],  a0, a1, a2, a3, bl0.z, bl0.w);
        mma_bf16(lin[0][2],  a0, a1, a2, a3, bl1.x, bl1.y);
        mma_bf16(lin[0][3],  a0, a1, a2, a3, bl1.z, bl1.w);
        mma_bf16(lin[1][0],  c0, c1, c2, c3, bl0.x, bl0.y);
        mma_bf16(lin[1][1],  c0, c1, c2, c3, bl0.z, bl0.w);
        mma_bf16(lin[1][2],  c0, c1, c2, c3, bl1.x, bl1.y);
        mma_bf16(lin[1][3],  c0, c1, c2, c3, bl1.z, bl1.w);
    }

    // ================= softmax over gate (rows split across 8 col groups) ===
    float mx[4] = {-1e30f, -1e30f, -1e30f, -1e30f};
    #pragma unroll
    for (int s = 0; s < 2; s++)
        #pragma unroll
        for (int t = 0; t < 4; t++) {
            int c = wq * 32 + t * 8 + tg * 2;
            gate[s][t][0] += bias[c];     gate[s][t][1] += bias[c + 1];
            gate[s][t][2] += bias[c];     gate[s][t][3] += bias[c + 1];
            mx[2 * s]     = fmaxf(mx[2 * s],     fmaxf(gate[s][t][0], gate[s][t][1]));
            mx[2 * s + 1] = fmaxf(mx[2 * s + 1], fmaxf(gate[s][t][2], gate[s][t][3]));
        }
    #pragma unroll
    for (int q = 0; q < 4; q++) {
        mx[q] = fmaxf(mx[q], __shfl_xor_sync(0xffffffffu, mx[q], 1));
        mx[q] = fmaxf(mx[q], __shfl_xor_sync(0xffffffffu, mx[q], 2));
    }
    if (tg == 0)
        #pragma unroll
        for (int q = 0; q < 4; q++) redmax[rows[q] * 8 + wq] = mx[q];
    __syncthreads();
    float m[4], sum[4] = {0.f, 0.f, 0.f, 0.f};
    #pragma unroll
    for (int q = 0; q < 4; q++) {
        const float* rm = &redmax[rows[q] * 8];
        float v = rm[0];
        #pragma unroll
        for (int j = 1; j < 8; j++) v = fmaxf(v, rm[j]);
        m[q] = v;
    }
    #pragma unroll
    for (int s = 0; s < 2; s++)
        #pragma unroll
        for (int t = 0; t < 4; t++) {
            gate[s][t][0] = __expf(gate[s][t][0] - m[2 * s]);
            gate[s][t][1] = __expf(gate[s][t][1] - m[2 * s]);
            gate[s][t][2] = __expf(gate[s][t][2] - m[2 * s + 1]);
            gate[s][t][3] = __expf(gate[s][t][3] - m[2 * s + 1]);
            sum[2 * s]     += gate[s][t][0] + gate[s][t][1];
            sum[2 * s + 1] += gate[s][t][2] + gate[s][t][3];
        }
    #pragma unroll
    for (int q = 0; q < 4; q++) {
        sum[q] += __shfl_xor_sync(0xffffffffu, sum[q], 1);
        sum[q] += __shfl_xor_sync(0xffffffffu, sum[q], 2);
    }
    if (tg == 0)
        #pragma unroll
        for (int q = 0; q < 4; q++) redsum[rows[q] * 8 + wq] = sum[q];
    __syncthreads();
    float invr[4];
    #pragma unroll
    for (int q = 0; q < 4; q++) {
        const float* rs = &redsum[rows[q] * 8];
        float v = rs[0];
        #pragma unroll
        for (int j = 1; j < 8; j++) v += rs[j];
        invr[q] = 1.f / v;
    }

    // ================= gated product -> bf16 staging in xs ==================
    // (all xs reads finished: the redmax __syncthreads above ordered them)
    #pragma unroll
    for (int s = 0; s < 2; s++)
        #pragma unroll
        for (int t = 0; t < 4; t++) {
            int c  = wq * 32 + t * 8 + tg * 2;
            int cp = c >> 1;
            float b0 = bias[256 + c], b1 = bias[256 + c + 1];
            float v0 = (lin[s][t][0] + b0) * gate[s][t][0] * invr[2 * s];
            float v1 = (lin[s][t][1] + b1) * gate[s][t][1] * invr[2 * s];
            float v2 = (lin[s][t][2] + b0) * gate[s][t][2] * invr[2 * s + 1];
            float v3 = (lin[s][t][3] + b1) * gate[s][t][3] * invr[2 * s + 1];
            xs[rows[2 * s]     * XS_STRIDE + cp] = packbf(v0, v1);
            xs[rows[2 * s + 1] * XS_STRIDE + cp] = packbf(v2, v3);
        }
    __syncthreads();

    // ================= segment reduce (sorted batch), few atomics ===========
    // 512 threads: col = tid&255 (2 bf16 per uint32 -> handled by hi bit),
    // rows split in halves between tid<256 and tid>=256? Simpler: each thread
    // owns one (col, row-half): col pair cp = (tid&255)>>1, hi = tid&1,
    // rhalf = tid>>8 -> rows [rhalf*32, rhalf*32+32).
    {
        const int cp = (tid & 255) >> 1, hi = tid & 1, rh = tid >> 8;
        const int col = (tid & 255);
        float run = 0.f;
        int cur = -1;
        for (int r = rh * 32; r < rh * 32 + 32; r++) {
            int g = bid[r];
            if (g != cur) {
                if (cur >= 0) atomicAdd(&g_sums[cur * CDIM + col], run);
                run = 0.f;
                cur = g;
            }
            if (g >= 0) {
                uint32_t u = xs[r * XS_STRIDE + cp];
                __nv_bfloat162 h = *reinterpret_cast<__nv_bfloat162*>(&u);
                run += hi ? __bfloat162float(h.y) : __bfloat162float(h.x);
            }
        }
        if (cur >= 0) atomicAdd(&g_sums[cur * CDIM + col], run);
    }
}

// out[g][c] = b_fin[c] + sum_k (sums[g][k]/max(cnt,1)) * W_fin[k][c]
// 4 graphs per block: W_fin L2 traffic / 4. counts via binary search.
__global__ void final_kernel(const int* __restrict__ batch, int N,
                             const float* __restrict__ W_fin,
                             const float* __restrict__ b_fin,
                             float* __restrict__ out) {
    __shared__ float mrow[4][CDIM];
    __shared__ int bounds[5];
    int g0 = blockIdx.x * 4, t = threadIdx.x;
    if (t < 5) {
        int key = g0 + t;
        int lo = 0, hi = N;
        while (lo < hi) { int m = (lo + hi) >> 1; if (batch[m] < key) lo = m + 1; else hi = m; }
        bounds[t] = lo;
    }
    __syncthreads();
    #pragma unroll
    for (int j = 0; j < 4; j++) {
        float invc = 1.f / fmaxf((float)(bounds[j + 1] - bounds[j]), 1.f);
        mrow[j][t] = g_sums[(g0 + j) * CDIM + t] * invc;
    }
    __syncthreads();
    float a0 = b_fin[t], a1 = a0, a2 = a0, a3 = a0;
    #pragma unroll 4
    for (int k = 0; k < CDIM; k++) {
        float wv = W_fin[k * CDIM + t];
        a0 = fmaf(mrow[0][k], wv, a0);
        a1 = fmaf(mrow[1][k], wv, a1);
        a2 = fmaf(mrow[2][k], wv, a2);
        a3 = fmaf(mrow[3][k], wv, a3);
    }
    out[(g0 + 0) * CDIM + t] = a0;
    out[(g0 + 1) * CDIM + t] = a1;
    out[(g0 + 2) * CDIM + t] = a2;
    out[(g0 + 3) * CDIM + t] = a3;
}

// ---------------------------------------------------------------------------
extern "C" void kernel_launch(void* const* d_in, const int* in_sizes, int n_in,
                              void* d_out, int out_size) {
    const float* x      = (const float*)d_in[0];
    // d_in[1] = edge_index (int32) : unused by the reference computation
    const int*   batch  = (const int*)d_in[2];     // jax x64 disabled -> int32
    const float* W_lin  = (const float*)d_in[3];
    const float* b_lin  = (const float*)d_in[4];
    const float* W_gate = (const float*)d_in[5];
    const float* b_gate = (const float*)d_in[6];
    const float* W_fin  = (const float*)d_in[7];
    const float* b_fin  = (const float*)d_in[8];
    float*       out    = (float*)d_out;

    int N = in_sizes[0] / CDIM;

    static bool attr_done = false;
    if (!attr_done) {
        cudaFuncSetAttribute(main_kernel, cudaFuncAttributeMaxDynamicSharedMemorySize,
                             SMEM_TOTAL);
        attr_done = true;
    }

    zero_sums_kernel<<<(GRAPHS * CDIM + 255) / 256, 256>>>();
    prep_weights_kernel<<<(16 * 2 * 16 * 32 + 255) / 256, 256>>>(W_gate, W_lin);

    int blocks = (N + 63) / 64;
    main_kernel<<<blocks, 512, SMEM_TOTAL>>>(x, batch, b_lin, b_gate, N);

    final_kernel<<<GRAPHS / 4, CDIM>>>(batch, N, W_fin, b_fin, out);
}

// round 11
// speedup vs baseline: 1.7099x; 1.7099x over previous
#include <cuda_runtime.h>
#include <cuda_bf16.h>
#include <cstdint>

#define GRAPHS 512
#define CDIM 256

// ---- device scratch (no allocations allowed) ----
// B fragments packed as uint4: [s][kt][ntp][lane], ntp = nt/2 pairs (2 n-tiles)
__device__ uint4 g_Bfrag[2 * 16 * 16 * 32];   // 256 KB
__device__ float g_sums[GRAPHS * CDIM];       // 512 KB: pooled sums

static __device__ __forceinline__ uint32_t packbf(float a, float b) {
    __nv_bfloat162 h = __float22bfloat162_rn(make_float2(a, b));
    return *reinterpret_cast<uint32_t*>(&h);
}

// ---------------------------------------------------------------------------
__global__ void zero_sums_kernel() {
    int i = blockIdx.x * blockDim.x + threadIdx.x;
    if (i < GRAPHS * CDIM) g_sums[i] = 0.f;
}

// Pack W_gate (s=0) and W_lin (s=1) into paired m16n8k16 B fragments:
// idx = ((s*16 + kt)*16 + ntp)*32 + lane ; covers n-tiles 2*ntp and 2*ntp+1.
// n = nt*8 + lane/4, k0 = kt*16 + (lane%4)*2
__global__ void prep_weights_kernel(const float* __restrict__ Wg,
                                    const float* __restrict__ Wl) {
    int i = blockIdx.x * blockDim.x + threadIdx.x;
    if (i >= 2 * 16 * 16 * 32) return;
    int lane = i & 31;
    int ntp  = (i >> 5) & 15;
    int kt   = (i >> 9) & 15;
    int s    = i >> 13;
    const float* W = s ? Wl : Wg;
    int n0 = (2 * ntp) * 8 + (lane >> 2);
    int n1 = n0 + 8;
    int k0 = kt * 16 + (lane & 3) * 2;
    uint4 v;
    v.x = packbf(W[(k0 + 0) * CDIM + n0], W[(k0 + 1) * CDIM + n0]);
    v.y = packbf(W[(k0 + 8) * CDIM + n0], W[(k0 + 9) * CDIM + n0]);
    v.z = packbf(W[(k0 + 0) * CDIM + n1], W[(k0 + 1) * CDIM + n1]);
    v.w = packbf(W[(k0 + 8) * CDIM + n1], W[(k0 + 9) * CDIM + n1]);
    g_Bfrag[i] = v;
}

// ---------------------------------------------------------------------------
static __device__ __forceinline__ void mma_bf16(float acc[4],
                                                uint32_t a0, uint32_t a1,
                                                uint32_t a2, uint32_t a3,
                                                uint32_t b0, uint32_t b1) {
    asm volatile(
        "mma.sync.aligned.m16n8k16.row.col.f32.bf16.bf16.f32 "
        "{%0,%1,%2,%3}, {%4,%5,%6,%7}, {%8,%9}, {%0,%1,%2,%3};\n"
        : "+f"(acc[0]), "+f"(acc[1]), "+f"(acc[2]), "+f"(acc[3])
        : "r"(a0), "r"(a1), "r"(a2), "r"(a3), "r"(b0), "r"(b1));
}

static __device__ __forceinline__ void ldsm4(uint32_t& a0, uint32_t& a1,
                                             uint32_t& a2, uint32_t& a3,
                                             uint32_t addr) {
    asm volatile("ldmatrix.sync.aligned.m8n8.x4.shared.b16 {%0,%1,%2,%3}, [%4];"
                 : "=r"(a0), "=r"(a1), "=r"(a2), "=r"(a3) : "r"(addr));
}

static __device__ __forceinline__ void cp_async16(uint32_t smem_dst, const void* gsrc) {
    asm volatile("cp.async.cg.shared.global [%0], [%1], 16;\n"
                 :: "r"(smem_dst), "l"(gsrc));
}
static __device__ __forceinline__ void cp_commit() {
    asm volatile("cp.async.commit_group;\n");
}
// RACE FIX (R10 post-mortem): wait_group 1, NOT 2. With prologue committing
// {G_kt, G_kt+1}, wait_group 2 lets the slab consumed THIS iteration still be
// in flight -> stale smem on replays. wait_group 1 guarantees G_kt resident
// while keeping G_kt+1 / G_kt+2 in flight (overlap depth still 2).
static __device__ __forceinline__ void cp_wait1() {
    asm volatile("cp.async.wait_group 1;\n");
}

// Fused pipeline. Warp tile: 32 rows (2 x m16) x 64 cols (8 n-tiles).
// Block: 64 nodes, 256 threads = 2 row-groups x 4 col-quarters.
#define XS_STRIDE 132                  // 128 uint32 + 4 pad
#define SLAB_U4   512                  // 16 ntp * 32 lanes, uint4 (8 KB)
// dynamic smem layout (bytes):
#define XS_OFF     0                   // 64*132*4 = 33792
#define BSM_OFF    33792               // 3*8192   = 24576
#define GSM_OFF    58368               // 64*132*4 = 33792 (gate exp bf16x2)
#define BIAS_OFF   92160               // 512*4    = 2048
#define RMAX_OFF   94208               // 256*4
#define RSUM_OFF   95232               // 256*4
#define BID_OFF    96256               // 64*4
#define SMEM_TOTAL 96512

__global__ __launch_bounds__(256, 2) void main_kernel(
    const float* __restrict__ x, const int* __restrict__ batch,
    const float* __restrict__ b_lin, const float* __restrict__ b_gate, int N) {
    extern __shared__ char smraw[];
    uint32_t* xs     = reinterpret_cast<uint32_t*>(smraw + XS_OFF);
    uint4*    bsm    = reinterpret_cast<uint4*>(smraw + BSM_OFF);
    uint32_t* gsm    = reinterpret_cast<uint32_t*>(smraw + GSM_OFF);
    float*    bias   = reinterpret_cast<float*>(smraw + BIAS_OFF);
    float*    redmax = reinterpret_cast<float*>(smraw + RMAX_OFF);
    float*    redsum = reinterpret_cast<float*>(smraw + RSUM_OFF);
    int*      bid    = reinterpret_cast<int*>(smraw + BID_OFF);

    const int tid   = threadIdx.x;
    const int node0 = blockIdx.x * 64;

    const uint32_t bsm_s = (uint32_t)__cvta_generic_to_shared(bsm);
    const uint32_t xs_s  = (uint32_t)__cvta_generic_to_shared(xs);

    // prefetch slabs (s=0, kt=0,1) immediately — overlaps with x-tile load
    {
        const char* src0 = (const char*)(g_Bfrag + (size_t)0 * SLAB_U4);
        cp_async16(bsm_s + 0 * 8192 + tid * 16, src0 + tid * 16);
        cp_async16(bsm_s + 0 * 8192 + (tid + 256) * 16, src0 + (tid + 256) * 16);
        cp_commit();
        const char* src1 = (const char*)(g_Bfrag + (size_t)1 * SLAB_U4);
        cp_async16(bsm_s + 1 * 8192 + tid * 16, src1 + tid * 16);
        cp_async16(bsm_s + 1 * 8192 + (tid + 256) * 16, src1 + (tid + 256) * 16);
        cp_commit();
    }

    // load x tile as packed bf16x2 (coalesced float2 reads)
    for (int i = tid; i < 64 * 128; i += 256) {
        int r = i >> 7, cp = i & 127;
        float2 v = make_float2(0.f, 0.f);
        if (node0 + r < N)
            v = reinterpret_cast<const float2*>(x)[(size_t)(node0 + r) * 128 + cp];
        xs[r * XS_STRIDE + cp] = packbf(v.x, v.y);
    }
    bias[tid]       = b_gate[tid];
    bias[256 + tid] = b_lin[tid];
    if (tid < 64) {
        int nd = node0 + tid;
        bid[tid] = (nd < N) ? batch[nd] : -1;
    }
    __syncthreads();

    const int lane = tid & 31, w = tid >> 5;
    const int wr = w >> 2;                // row group 0..1
    const int wq = w & 3;                 // column quarter 0..3
    const int r0 = wr * 32, gid = lane >> 2, tg = lane & 3;
    const int ra0 = r0 + gid,      rb0 = ra0 + 8;
    const int ra1 = r0 + 16 + gid, rb1 = ra1 + 8;

    const int lr = ((lane >> 3) & 1) * 8 + (lane & 7);
    const uint32_t a_addr0 = xs_s + 4u * (uint32_t)((r0 + lr) * XS_STRIDE + (lane >> 4) * 4);
    const uint32_t a_addr1 = xs_s + 4u * (uint32_t)((r0 + 16 + lr) * XS_STRIDE + (lane >> 4) * 4);

    float invr[4];   // 1/sum for ra0, rb0, ra1, rb1

    // ================= GEMM 1: gate logits ==================================
    {
        float gate[2][8][4];
        #pragma unroll
        for (int s = 0; s < 2; s++)
            #pragma unroll
            for (int t = 0; t < 8; t++)
                gate[s][t][0] = gate[s][t][1] = gate[s][t][2] = gate[s][t][3] = 0.f;
        for (int kt = 0; kt < 16; kt++) {
            cp_wait1();            // slab kt GUARANTEED resident
            __syncthreads();
            int nxt = kt + 2;
            if (nxt < 16) {
                const char* src = (const char*)(g_Bfrag + (size_t)nxt * SLAB_U4);
                uint32_t dst = bsm_s + (nxt % 3) * 8192;
                cp_async16(dst + tid * 16, src + tid * 16);
                cp_async16(dst + (tid + 256) * 16, src + (tid + 256) * 16);
            }
            cp_commit();
            uint32_t a0, a1, a2, a3, c0, c1, c2, c3;
            ldsm4(a0, a1, a2, a3, a_addr0 + (uint32_t)kt * 32);
            ldsm4(c0, c1, c2, c3, a_addr1 + (uint32_t)kt * 32);
            const uint4* bp = bsm + (kt % 3) * SLAB_U4 + (wq * 4) * 32 + lane;
            #pragma unroll
            for (int j = 0; j < 4; j++) {
                uint4 bq = bp[j * 32];
                mma_bf16(gate[0][2 * j],     a0, a1, a2, a3, bq.x, bq.y);
                mma_bf16(gate[0][2 * j + 1], a0, a1, a2, a3, bq.z, bq.w);
                mma_bf16(gate[1][2 * j],     c0, c1, c2, c3, bq.x, bq.y);
                mma_bf16(gate[1][2 * j + 1], c0, c1, c2, c3, bq.z, bq.w);
            }
        }
        __syncthreads();
        // prefetch first two slabs of GEMM2 (s=1 -> slabs 16,17)
        {
            const char* src0 = (const char*)(g_Bfrag + (size_t)16 * SLAB_U4);
            cp_async16(bsm_s + (16 % 3) * 8192 + tid * 16, src0 + tid * 16);
            cp_async16(bsm_s + (16 % 3) * 8192 + (tid + 256) * 16, src0 + (tid + 256) * 16);
            cp_commit();
            const char* src1 = (const char*)(g_Bfrag + (size_t)17 * SLAB_U4);
            cp_async16(bsm_s + (17 % 3) * 8192 + tid * 16, src1 + tid * 16);
            cp_async16(bsm_s + (17 % 3) * 8192 + (tid + 256) * 16, src1 + (tid + 256) * 16);
            cp_commit();
        }

        // bias + per-thread max over its columns, per row
        float mx[4] = {-1e30f, -1e30f, -1e30f, -1e30f};
        #pragma unroll
        for (int s = 0; s < 2; s++)
            #pragma unroll
            for (int t = 0; t < 8; t++) {
                int c = wq * 64 + t * 8 + tg * 2;
                gate[s][t][0] += bias[c];     gate[s][t][1] += bias[c + 1];
                gate[s][t][2] += bias[c];     gate[s][t][3] += bias[c + 1];
                mx[2 * s]     = fmaxf(mx[2 * s],     fmaxf(gate[s][t][0], gate[s][t][1]));
                mx[2 * s + 1] = fmaxf(mx[2 * s + 1], fmaxf(gate[s][t][2], gate[s][t][3]));
            }
        #pragma unroll
        for (int q = 0; q < 4; q++) {
            mx[q] = fmaxf(mx[q], __shfl_xor_sync(0xffffffffu, mx[q], 1));
            mx[q] = fmaxf(mx[q], __shfl_xor_sync(0xffffffffu, mx[q], 2));
        }
        if (tg == 0) {
            redmax[ra0 * 4 + wq] = mx[0];
            redmax[rb0 * 4 + wq] = mx[1];
            redmax[ra1 * 4 + wq] = mx[2];
            redmax[rb1 * 4 + wq] = mx[3];
        }
        __syncthreads();
        const int rows[4] = {ra0, rb0, ra1, rb1};
        float m[4], sum[4] = {0.f, 0.f, 0.f, 0.f};
        #pragma unroll
        for (int q = 0; q < 4; q++) {
            float* rm = &redmax[rows[q] * 4];
            m[q] = fmaxf(fmaxf(rm[0], rm[1]), fmaxf(rm[2], rm[3]));
        }
        #pragma unroll
        for (int s = 0; s < 2; s++)
            #pragma unroll
            for (int t = 0; t < 8; t++) {
                float e0 = __expf(gate[s][t][0] - m[2 * s]);
                float e1 = __expf(gate[s][t][1] - m[2 * s]);
                float e2 = __expf(gate[s][t][2] - m[2 * s + 1]);
                float e3 = __expf(gate[s][t][3] - m[2 * s + 1]);
                sum[2 * s]     += e0 + e1;
                sum[2 * s + 1] += e2 + e3;
                int cp = (wq * 64 + t * 8 + tg * 2) >> 1;
                gsm[rows[2 * s]     * XS_STRIDE + cp] = packbf(e0, e1);
                gsm[rows[2 * s + 1] * XS_STRIDE + cp] = packbf(e2, e3);
            }
        #pragma unroll
        for (int q = 0; q < 4; q++) {
            sum[q] += __shfl_xor_sync(0xffffffffu, sum[q], 1);
            sum[q] += __shfl_xor_sync(0xffffffffu, sum[q], 2);
        }
        if (tg == 0) {
            redsum[ra0 * 4 + wq] = sum[0];
            redsum[rb0 * 4 + wq] = sum[1];
            redsum[ra1 * 4 + wq] = sum[2];
            redsum[rb1 * 4 + wq] = sum[3];
        }
        __syncthreads();
        #pragma unroll
        for (int q = 0; q < 4; q++) {
            float* rs = &redsum[rows[q] * 4];
            invr[q] = 1.f / (rs[0] + rs[1] + rs[2] + rs[3]);
        }
    }

    // ================= GEMM 2: states =======================================
    float acc[2][8][4];
    #pragma unroll
    for (int s = 0; s < 2; s++)
        #pragma unroll
        for (int t = 0; t < 8; t++)
            acc[s][t][0] = acc[s][t][1] = acc[s][t][2] = acc[s][t][3] = 0.f;
    for (int kt = 0; kt < 16; kt++) {
        cp_wait1();
        __syncthreads();
        int nxt = kt + 2;
        if (nxt < 16) {
            const char* src = (const char*)(g_Bfrag + (size_t)(16 + nxt) * SLAB_U4);
            uint32_t dst = bsm_s + ((16 + nxt) % 3) * 8192;
            cp_async16(dst + tid * 16, src + tid * 16);
            cp_async16(dst + (tid + 256) * 16, src + (tid + 256) * 16);
        }
        cp_commit();
        uint32_t a0, a1, a2, a3, c0, c1, c2, c3;
        ldsm4(a0, a1, a2, a3, a_addr0 + (uint32_t)kt * 32);
        ldsm4(c0, c1, c2, c3, a_addr1 + (uint32_t)kt * 32);
        const uint4* bp = bsm + ((16 + kt) % 3) * SLAB_U4 + (wq * 4) * 32 + lane;
        #pragma unroll
        for (int j = 0; j < 4; j++) {
            uint4 bq = bp[j * 32];
            mma_bf16(acc[0][2 * j],     a0, a1, a2, a3, bq.x, bq.y);
            mma_bf16(acc[0][2 * j + 1], a0, a1, a2, a3, bq.z, bq.w);
            mma_bf16(acc[1][2 * j],     c0, c1, c2, c3, bq.x, bq.y);
            mma_bf16(acc[1][2 * j + 1], c0, c1, c2, c3, bq.z, bq.w);
        }
    }
    __syncthreads();   // all warps done reading xs; safe to overwrite

    // gated product (gate exp read back from gsm), staged into xs bf16x2
    {
        const int rows[4] = {ra0, rb0, ra1, rb1};
        #pragma unroll
        for (int s = 0; s < 2; s++)
            #pragma unroll
            for (int t = 0; t < 8; t++) {
                int c  = wq * 64 + t * 8 + tg * 2;
                int cp = c >> 1;
                float b0 = bias[256 + c], b1 = bias[256 + c + 1];
                uint32_t ga = gsm[rows[2 * s]     * XS_STRIDE + cp];
                uint32_t gb = gsm[rows[2 * s + 1] * XS_STRIDE + cp];
                __nv_bfloat162 ha = *reinterpret_cast<__nv_bfloat162*>(&ga);
                __nv_bfloat162 hb = *reinterpret_cast<__nv_bfloat162*>(&gb);
                float v0 = (acc[s][t][0] + b0) * __bfloat162float(ha.x) * invr[2 * s];
                float v1 = (acc[s][t][1] + b1) * __bfloat162float(ha.y) * invr[2 * s];
                float v2 = (acc[s][t][2] + b0) * __bfloat162float(hb.x) * invr[2 * s + 1];
                float v3 = (acc[s][t][3] + b1) * __bfloat162float(hb.y) * invr[2 * s + 1];
                xs[rows[2 * s]     * XS_STRIDE + cp] = packbf(v0, v1);
                xs[rows[2 * s + 1] * XS_STRIDE + cp] = packbf(v2, v3);
            }
    }
    __syncthreads();

    // ================= segment reduce (sorted batch), few atomics ===========
    {
        const int cp = tid >> 1, hi = tid & 1;
        float run = 0.f;
        int cur = -1;
        for (int r = 0; r < 64; r++) {
            int g = bid[r];
            if (g != cur) {
                if (cur >= 0) atomicAdd(&g_sums[cur * CDIM + tid], run);
                run = 0.f;
                cur = g;
            }
            if (g >= 0) {
                uint32_t u = xs[r * XS_STRIDE + cp];
                __nv_bfloat162 h = *reinterpret_cast<__nv_bfloat162*>(&u);
                run += hi ? __bfloat162float(h.y) : __bfloat162float(h.x);
            }
        }
        if (cur >= 0) atomicAdd(&g_sums[cur * CDIM + tid], run);
    }
}

// out[g][c] = b_fin[c] + sum_k (sums[g][k]/max(cnt,1)) * W_fin[k][c]
// count computed per-block via binary search on sorted batch (L2-hot).
__global__ void final_kernel(const int* __restrict__ batch, int N,
                             const float* __restrict__ W_fin,
                             const float* __restrict__ b_fin,
                             float* __restrict__ out) {
    __shared__ float mrow[CDIM];
    __shared__ int bounds[2];
    int g = blockIdx.x, t = threadIdx.x;
    if (t < 2) {
        int key = g + t;
        int lo = 0, hi = N;
        while (lo < hi) { int m = (lo + hi) >> 1; if (batch[m] < key) lo = m + 1; else hi = m; }
        bounds[t] = lo;
    }
    __syncthreads();
    float invc = 1.f / fmaxf((float)(bounds[1] - bounds[0]), 1.f);
    mrow[t] = g_sums[g * CDIM + t] * invc;
    __syncthreads();
    float a = b_fin[t];
    #pragma unroll 8
    for (int k = 0; k < CDIM; k++) a = fmaf(mrow[k], W_fin[k * CDIM + t], a);
    out[g * CDIM + t] = a;
}

// ---------------------------------------------------------------------------
extern "C" void kernel_launch(void* const* d_in, const int* in_sizes, int n_in,
                              void* d_out, int out_size) {
    const float* x      = (const float*)d_in[0];
    // d_in[1] = edge_index (int32) : unused by the reference computation
    const int*   batch  = (const int*)d_in[2];     // jax x64 disabled -> int32
    const float* W_lin  = (const float*)d_in[3];
    const float* b_lin  = (const float*)d_in[4];
    const float* W_gate = (const float*)d_in[5];
    const float* b_gate = (const float*)d_in[6];
    const float* W_fin  = (const float*)d_in[7];
    const float* b_fin  = (const float*)d_in[8];
    float*       out    = (float*)d_out;

    int N = in_sizes[0] / CDIM;

    static bool attr_done = false;
    if (!attr_done) {
        cudaFuncSetAttribute(main_kernel, cudaFuncAttributeMaxDynamicSharedMemorySize,
                             SMEM_TOTAL);
        attr_done = true;
    }

    zero_sums_kernel<<<(GRAPHS * CDIM + 255) / 256, 256>>>();
    prep_weights_kernel<<<(2 * 16 * 16 * 32 + 255) / 256, 256>>>(W_gate, W_lin);

    int blocks = (N + 63) / 64;
    main_kernel<<<blocks, 256, SMEM_TOTAL>>>(x, batch, b_lin, b_gate, N);

    final_kernel<<<GRAPHS, CDIM>>>(batch, N, W_fin, b_fin, out);
}